// round 12
// baseline (speedup 1.0000x reference)
#include <cuda_runtime.h>
#include <cuda_fp16.h>
#include <cstdint>

#define BB 256
#define TT 2048

// ---------- scratch ----------
__device__ __half g_out1h[(size_t)BB * TT * 128];     // layer-1 output fp16 [B,T,128] (fwd|bwd)
__device__ float  g_pre2p[(size_t)BB * TT * 256];     // l2 input preact, permuted, bias folded (i,f,o pre-halved)
__device__ __half g_B1[2][256 * 80];                  // l1 fused B [n][k]: [Whh_hi(64)|Wih_hi(4)|Wih_lo(4)|0(8)]
__device__ __half g_B2s[256 * 64];                    // l2 scan B: Whh2_hi, i/f/o halved
__device__ __half g_B2i[256 * 128];                   // pre2 GEMM B: Wih2 fp16, col n2=j*4+gate, i/f/o halved

// ---------- helpers ----------
__device__ __forceinline__ float tanh_f(float x) {
    float y; asm("tanh.approx.f32 %0, %1;" : "=f"(y) : "f"(x)); return y;
}
// x is PRE-HALVED preactivation
__device__ __forceinline__ float sig_h(float x) {
    return fmaf(tanh_f(x), 0.5f, 0.5f);
}
__device__ __forceinline__ __half hi_h(float v) { return __float2half_rn(v); }
__device__ __forceinline__ __half lo_h(float v) {
    return __float2half_rn(v - __half2float(__float2half_rn(v)));
}
__device__ __forceinline__ uint32_t smem_u32(const void* p) {
    uint32_t a;
    asm("{ .reg .u64 t; cvta.to.shared.u64 t, %1; cvt.u32.u64 %0, t; }" : "=r"(a) : "l"(p));
    return a;
}
// load 2 8x8 matrices: rows 0-7 of A, k-halves [0:8) and [8:16) of a kt
__device__ __forceinline__ void ldsm2(uint32_t* r, uint32_t addr) {
    asm volatile("ldmatrix.sync.aligned.m8n8.x2.shared.b16 {%0,%1}, [%2];"
                 : "=r"(r[0]), "=r"(r[1]) : "r"(addr));
}
// mma with rows 8-15 = 0 (a1 = a3 = 0)
__device__ __forceinline__ void mma_z(float* d, uint32_t a0, uint32_t a2, const uint32_t* b) {
    asm volatile("mma.sync.aligned.m16n8k16.row.col.f32.f16.f16.f32 "
                 "{%0,%1,%2,%3},{%4,%5,%6,%7},{%8,%9},{%0,%1,%2,%3};"
                 : "+f"(d[0]), "+f"(d[1]), "+f"(d[2]), "+f"(d[3])
                 : "r"(a0), "r"(0u), "r"(a2), "r"(0u), "r"(b[0]), "r"(b[1]));
}

// gate-permuted column map (adjacent-j):
// tile = n>>3, c = n&7; wq = tile>>2, u = (tile>>1)&1, odd = tile&1
// j = wq*8 + 2*(c>>1) + u ; gate = 2*odd + (c&1) ; row = gate*64 + j
__device__ __forceinline__ int perm_row(int n) {
    int tile = n >> 3, c = n & 7;
    int wq = tile >> 2, u = (tile >> 1) & 1, odd = tile & 1;
    int j = wq * 8 + 2 * (c >> 1) + u;
    int gate = 2 * odd + (c & 1);
    return gate * 64 + j;
}

// =====================================================================
// Build fused B matrices (sigmoid-gate rows pre-halved).
// =====================================================================
__global__ void build_B(const float* __restrict__ Wih_f, const float* __restrict__ Whh_f,
                        const float* __restrict__ Wih_b, const float* __restrict__ Whh_b,
                        const float* __restrict__ Wih2,  const float* __restrict__ Whh2)
{
    const int n = blockIdx.x;
    const int k = threadIdx.x;
    const int r = perm_row(n);
    const float s = ((r >> 6) == 2) ? 1.f : 0.5f;   // g gate unscaled

    if (k < 80) {
        __half vf, vb;
        if      (k < 64) { vf = hi_h(s * Whh_f[r * 64 + k]);        vb = hi_h(s * Whh_b[r * 64 + k]); }
        else if (k < 68) { vf = hi_h(s * Wih_f[r * 4 + (k - 64)]);  vb = hi_h(s * Wih_b[r * 4 + (k - 64)]); }
        else if (k < 72) { vf = hi_h(s * Wih_f[r * 4 + (k - 68)]);  vb = hi_h(s * Wih_b[r * 4 + (k - 68)]); }
        else             { vf = __ushort_as_half(0);                vb = __ushort_as_half(0); }
        g_B1[0][n * 80 + k] = vf;
        g_B1[1][n * 80 + k] = vb;
    }
    if (k < 64) {
        g_B2s[n * 64 + k] = hi_h(s * Whh2[r * 64 + k]);
    }
    if (k < 128) {
        const int g2 = n & 3;
        const int r2 = g2 * 64 + (n >> 2);
        const float s2 = (g2 == 2) ? 1.f : 0.5f;
        g_B2i[n * 128 + k] = __float2half_rn(s2 * Wih2[r2 * 128 + k]);
    }
}

// =====================================================================
// Layer-1 scan: 8 samples/block, one direction. 64 blocks, 256 threads.
// A[8 x 80] fp16 (stride 88): [h_hi(64) | x_hi(4) | x_lo(4) | pad]. 5 kt.
// ldsm.x2 (rows 0-7 only), upper MMA fragments constant-zero.
// =====================================================================
#define AS1 88
__global__ __launch_bounds__(256, 1)
void l1_scan(const float* __restrict__ x,
             const float* __restrict__ b_f, const float* __restrict__ b_b)
{
    const int grp = blockIdx.x >> 1;
    const int dir = blockIdx.x & 1;
    const int s0  = grp * 8;
    const int tid = threadIdx.x, lane = tid & 31, w = tid >> 5;

    __shared__ __half A[2 * 8 * AS1];

    for (int i = tid; i < 2 * 8 * AS1; i += 256) A[i] = __ushort_as_half(0);

    // B fragments: warp w owns n8-tiles 4w..4w+3 (u = tt>>1, odd = tt&1)
    uint32_t bf[4][5][2];
    {
        const __half* B = g_B1[dir];
#pragma unroll
        for (int tt = 0; tt < 4; tt++) {
            const int n = (w * 4 + tt) * 8 + (lane >> 2);
#pragma unroll
            for (int kt = 0; kt < 5; kt++) {
                const __half* p = B + (size_t)n * 80 + kt * 16 + 2 * (lane & 3);
                bf[tt][kt][0] = *(const uint32_t*)p;
                bf[tt][kt][1] = *(const uint32_t*)(p + 8);
            }
        }
    }

    // cells: j0 (u=0, tiles 0,1), j1 = j0+1 (u=1, tiles 2,3)
    const int srow = lane >> 2;
    const int j0 = w * 8 + 2 * (lane & 3), j1 = j0 + 1;
    const float* bv = dir ? b_b : b_f;
    const float bi0 = 0.5f * bv[j0], bff0 = 0.5f * bv[64 + j0], bg0 = bv[128 + j0], bo0 = 0.5f * bv[192 + j0];
    const float bi1 = 0.5f * bv[j1], bff1 = 0.5f * bv[64 + j1], bg1 = bv[128 + j1], bo1 = 0.5f * bv[192 + j1];

    // ldsm.x2 lane addressing: lanes 0-15 -> (row = lane&7, matrix = (lane>>3)&1)
    const uint32_t lr = lane & 7, lm = (lane >> 3) & 1;
    const uint32_t aaddr0 = smem_u32(A) + (lr * AS1 + lm * 8) * 2;
    const uint32_t aaddr1 = aaddr0 + 8 * AS1 * 2;

    const int step = dir ? -1 : 1;
    const int t0   = dir ? TT - 1 : 0;

    // x feeder: threads 0..31 (sample fsx, component comp)
    const bool xf = tid < 32;
    const int fsx = tid >> 2, comp = tid & 3;
    const float* xp = x + ((size_t)(s0 + fsx) * TT + t0) * 4 + comp;
    float vn = 0.f, vi = 0.f;
    if (xf) {
        float v0 = __ldg(xp);
        A[fsx * AS1 + 64 + comp] = hi_h(v0);
        A[fsx * AS1 + 68 + comp] = lo_h(v0);
        vn = __ldg(xp + step * 4);
        vi = __ldg(xp + 2 * step * 4);
    }
    __syncthreads();

    const int ffs = tid >> 4, ffc = tid & 15;
    __half* fout = g_out1h + (size_t)(s0 + ffs) * TT * 128 + dir * 64 + ffc * 4;

    float c0 = 0.f, c1 = 0.f;

    for (int t = 0; t < TT; t++) {
        const int cur = t & 1, nxt = cur ^ 1;
        const uint32_t aaddr = cur ? aaddr1 : aaddr0;
        __half* An = A + nxt * 8 * AS1;

        // 2-way split k accumulation (kt 0-2 / 3-4), a1=a3=0 (rows 8-15)
        float aA0[4], aB0[4], aA1[4], aB1[4];
#pragma unroll
        for (int q = 0; q < 4; q++) { aA0[q] = 0.f; aB0[q] = 0.f; aA1[q] = 0.f; aB1[q] = 0.f; }
#pragma unroll
        for (int kt = 0; kt < 5; kt++) {
            uint32_t a[2];
            ldsm2(a, aaddr + kt * 32);
            if (kt < 3) {
                mma_z(aA0, a[0], a[1], bf[0][kt]); mma_z(aA0 + 0 == aA0 ? aA0 : aA0, a[0], a[1], bf[0][kt]); // placeholder removed below
            }
        }
        // (rewritten cleanly)
        {
#pragma unroll
            for (int q = 0; q < 4; q++) { aA0[q] = 0.f; aB0[q] = 0.f; aA1[q] = 0.f; aB1[q] = 0.f; }
            float aA2[4], aB2[4], aA3[4], aB3[4];
#pragma unroll
            for (int q = 0; q < 4; q++) { aA2[q] = 0.f; aB2[q] = 0.f; aA3[q] = 0.f; aB3[q] = 0.f; }
#pragma unroll
            for (int kt = 0; kt < 5; kt++) {
                uint32_t a[2];
                ldsm2(a, aaddr + kt * 32);
                if (kt < 3) {
                    mma_z(aA0, a[0], a[1], bf[0][kt]);
                    mma_z(aA1, a[0], a[1], bf[1][kt]);
                    mma_z(aA2, a[0], a[1], bf[2][kt]);
                    mma_z(aA3, a[0], a[1], bf[3][kt]);
                } else {
                    mma_z(aB0, a[0], a[1], bf[0][kt]);
                    mma_z(aB1, a[0], a[1], bf[1][kt]);
                    mma_z(aB2, a[0], a[1], bf[2][kt]);
                    mma_z(aB3, a[0], a[1], bf[3][kt]);
                }
            }

            // epilogue: cell j0 from tiles 0 (i,f) + 1 (g,o); cell j1 from tiles 2,3
            float iv = sig_h (aA0[0] + aB0[0] + bi0);
            float fv = sig_h (aA0[1] + aB0[1] + bff0);
            float gv = tanh_f(aA1[0] + aB1[0] + bg0);
            float ov = sig_h (aA1[1] + aB1[1] + bo0);
            c0 = fv * c0 + iv * gv;
            float h0 = ov * tanh_f(c0);

            iv = sig_h (aA2[0] + aB2[0] + bi1);
            fv = sig_h (aA2[1] + aB2[1] + bff1);
            gv = tanh_f(aA3[0] + aB3[0] + bg1);
            ov = sig_h (aA3[1] + aB3[1] + bo1);
            c1 = fv * c1 + iv * gv;
            float h1 = ov * tanh_f(c1);

            // STS early
            __half2 hhi = __floats2half2_rn(h0, h1);
            *(__half2*)&An[srow * AS1 + j0] = hhi;
        }

        // post-STS independent work (overlaps the store drain)
        if (xf) {
            An[fsx * AS1 + 64 + comp] = hi_h(vn);
            An[fsx * AS1 + 68 + comp] = lo_h(vn);
        }
        if (t && tid < 128) {
            const __half* Ac = A + cur * 8 * AS1;
            uint2 v = *(const uint2*)(Ac + ffs * AS1 + ffc * 4);
            *(uint2*)(fout + (size_t)(t0 + (t - 1) * step) * 128) = v;
        }
        if (xf) {
            vn = vi;
            vi = (t + 3 < TT) ? __ldg(xp + (size_t)(t + 3) * step * 4) : 0.f;
        }

        __syncthreads();
    }

    if (tid < 128) {
        uint2 v = *(const uint2*)(A + ffs * AS1 + ffc * 4);
        *(uint2*)(fout + (size_t)(t0 + (TT - 1) * step) * 128) = v;
    }
}

// =====================================================================
// pre2 GEMM: g_pre2p[m, n2] = sum_k out1h[m,k] * B2i[n2,k] + bias (scaled)
// =====================================================================
#define ASG 136
__global__ __launch_bounds__(256, 2)
void pre2_gemm(const float* __restrict__ b2)
{
    const int m0 = blockIdx.x * 128;
    const int tid = threadIdx.x, lane = tid & 31, w = tid >> 5;

    __shared__ __half As[128 * ASG];

    {
        const uint4* src = (const uint4*)(g_out1h + (size_t)m0 * 128);
        for (int i = tid; i < 128 * 16; i += 256) {
            int rr = i >> 4, cc = i & 15;
            *(uint4*)&As[rr * ASG + cc * 8] = __ldg(src + i);
        }
    }
    __syncthreads();

    const uint32_t aaddr = smem_u32(As) + (((w * 16) + (lane & 15)) * ASG + (lane >> 4) * 8) * 2;

    float* outp = g_pre2p + (size_t)(m0 + w * 16) * 256;
    const int row0 = lane >> 2;

#pragma unroll 1
    for (int ng = 0; ng < 8; ng++) {
        uint32_t bfr[4][8][2];
#pragma unroll
        for (int tt = 0; tt < 4; tt++) {
            const int n = ng * 32 + tt * 8 + (lane >> 2);
#pragma unroll
            for (int kt = 0; kt < 8; kt++) {
                const __half* p = g_B2i + (size_t)n * 128 + kt * 16 + 2 * (lane & 3);
                bfr[tt][kt][0] = *(const uint32_t*)p;
                bfr[tt][kt][1] = *(const uint32_t*)(p + 8);
            }
        }

        float acc[4][4];
#pragma unroll
        for (int i = 0; i < 4; i++) { acc[i][0] = 0.f; acc[i][1] = 0.f; acc[i][2] = 0.f; acc[i][3] = 0.f; }
#pragma unroll
        for (int kt = 0; kt < 8; kt++) {
            uint32_t a[4];
            asm volatile("ldmatrix.sync.aligned.m8n8.x4.shared.b16 {%0,%1,%2,%3}, [%4];"
                         : "=r"(a[0]), "=r"(a[1]), "=r"(a[2]), "=r"(a[3]) : "r"(aaddr + kt * 32));
            asm volatile("mma.sync.aligned.m16n8k16.row.col.f32.f16.f16.f32 "
                         "{%0,%1,%2,%3},{%4,%5,%6,%7},{%8,%9},{%0,%1,%2,%3};"
                         : "+f"(acc[0][0]), "+f"(acc[0][1]), "+f"(acc[0][2]), "+f"(acc[0][3])
                         : "r"(a[0]), "r"(a[1]), "r"(a[2]), "r"(a[3]), "r"(bfr[0][kt][0]), "r"(bfr[0][kt][1]));
            asm volatile("mma.sync.aligned.m16n8k16.row.col.f32.f16.f16.f32 "
                         "{%0,%1,%2,%3},{%4,%5,%6,%7},{%8,%9},{%0,%1,%2,%3};"
                         : "+f"(acc[1][0]), "+f"(acc[1][1]), "+f"(acc[1][2]), "+f"(acc[1][3])
                         : "r"(a[0]), "r"(a[1]), "r"(a[2]), "r"(a[3]), "r"(bfr[1][kt][0]), "r"(bfr[1][kt][1]));
            asm volatile("mma.sync.aligned.m16n8k16.row.col.f32.f16.f16.f32 "
                         "{%0,%1,%2,%3},{%4,%5,%6,%7},{%8,%9},{%0,%1,%2,%3};"
                         : "+f"(acc[2][0]), "+f"(acc[2][1]), "+f"(acc[2][2]), "+f"(acc[2][3])
                         : "r"(a[0]), "r"(a[1]), "r"(a[2]), "r"(a[3]), "r"(bfr[2][kt][0]), "r"(bfr[2][kt][1]));
            asm volatile("mma.sync.aligned.m16n8k16.row.col.f32.f16.f16.f32 "
                         "{%0,%1,%2,%3},{%4,%5,%6,%7},{%8,%9},{%0,%1,%2,%3};"
                         : "+f"(acc[3][0]), "+f"(acc[3][1]), "+f"(acc[3][2]), "+f"(acc[3][3])
                         : "r"(a[0]), "r"(a[1]), "r"(a[2]), "r"(a[3]), "r"(bfr[3][kt][0]), "r"(bfr[3][kt][1]));
        }

#pragma unroll
        for (int tt = 0; tt < 4; tt++) {
            const int col = ng * 32 + tt * 8 + 2 * (lane & 3);
            const int ra = (col & 3) * 64 + (col >> 2);
            const int rb = ((col + 1) & 3) * 64 + ((col + 1) >> 2);
            const float sa = ((col & 3) == 2) ? 1.f : 0.5f;
            const float ba = __ldg(b2 + ra) * sa;
            const float bb = __ldg(b2 + rb) * 0.5f;
            float2 v0 = make_float2(acc[tt][0] + ba, acc[tt][1] + bb);
            float2 v1 = make_float2(acc[tt][2] + ba, acc[tt][3] + bb);
            *(float2*)(outp + (size_t)row0 * 256 + col)       = v0;
            *(float2*)(outp + (size_t)(row0 + 8) * 256 + col) = v1;
        }
    }
}

// =====================================================================
// Layer-2 scan: 8 samples/block, 32 blocks, 256 threads. K=64, 4 kt.
// ldsm.x2 (rows 0-7), STS-early/barrier-late. Fused FC.
// =====================================================================
#define AS2 72
__global__ __launch_bounds__(256, 1)
void l2_scan(const float* __restrict__ Wfc, const float* __restrict__ bfc,
             float* __restrict__ out)
{
    const int s0  = blockIdx.x * 8;
    const int tid = threadIdx.x, lane = tid & 31, w = tid >> 5;

    __shared__ __half A[2 * 8 * AS2];
    __shared__ float  sred[8 * 64];

    for (int i = tid; i < 2 * 8 * AS2; i += 256) A[i] = __ushort_as_half(0);

    uint32_t bf[4][4][2];
#pragma unroll
    for (int tt = 0; tt < 4; tt++) {
        const int n = (w * 4 + tt) * 8 + (lane >> 2);
#pragma unroll
        for (int kt = 0; kt < 4; kt++) {
            const __half* p = g_B2s + (size_t)n * 64 + kt * 16 + 2 * (lane & 3);
            bf[tt][kt][0] = *(const uint32_t*)p;
            bf[tt][kt][1] = *(const uint32_t*)(p + 8);
        }
    }

    const int srow = lane >> 2;
    const int j0 = w * 8 + 2 * (lane & 3), j1 = j0 + 1;
    const float wf0 = __ldg(Wfc + j0), wf1 = __ldg(Wfc + j1);

    const uint32_t lr = lane & 7, lm = (lane >> 3) & 1;
    const uint32_t aaddr0 = smem_u32(A) + (lr * AS2 + lm * 8) * 2;
    const uint32_t aaddr1 = aaddr0 + 8 * AS2 * 2;

    // pre2 stream: two contiguous (i,f,g,o) quads per lane (j0, j1)
    const float* pp = g_pre2p + (size_t)(s0 + srow) * TT * 256 + j0 * 4;
    float4 pc0 = *(const float4*)(pp);
    float4 pc1 = *(const float4*)(pp + 4);
    float4 pn0 = *(const float4*)(pp + 256);
    float4 pn1 = *(const float4*)(pp + 260);
    __syncthreads();

    float c0 = 0.f, c1 = 0.f;
    float h0 = 0.f, h1 = 0.f;

    for (int t = 0; t < TT; t++) {
        const int cur = t & 1, nxt = cur ^ 1;
        const uint32_t aaddr = cur ? aaddr1 : aaddr0;
        __half* An = A + nxt * 8 * AS2;

        float aA0[4], aB0[4], aA1[4], aB1[4];
        float aA2[4], aB2[4], aA3[4], aB3[4];
#pragma unroll
        for (int q = 0; q < 4; q++) {
            aA0[q] = 0.f; aB0[q] = 0.f; aA1[q] = 0.f; aB1[q] = 0.f;
            aA2[q] = 0.f; aB2[q] = 0.f; aA3[q] = 0.f; aB3[q] = 0.f;
        }
#pragma unroll
        for (int kt = 0; kt < 4; kt++) {
            uint32_t a[2];
            ldsm2(a, aaddr + kt * 32);
            if (kt < 2) {
                mma_z(aA0, a[0], a[1], bf[0][kt]);
                mma_z(aA1, a[0], a[1], bf[1][kt]);
                mma_z(aA2, a[0], a[1], bf[2][kt]);
                mma_z(aA3, a[0], a[1], bf[3][kt]);
            } else {
                mma_z(aB0, a[0], a[1], bf[0][kt]);
                mma_z(aB1, a[0], a[1], bf[1][kt]);
                mma_z(aB2, a[0], a[1], bf[2][kt]);
                mma_z(aB3, a[0], a[1], bf[3][kt]);
            }
        }

        {
            float iv = sig_h (aA0[0] + aB0[0] + pc0.x);
            float fv = sig_h (aA0[1] + aB0[1] + pc0.y);
            float gv = tanh_f(aA1[0] + aB1[0] + pc0.z);
            float ov = sig_h (aA1[1] + aB1[1] + pc0.w);
            c0 = fv * c0 + iv * gv;
            h0 = ov * tanh_f(c0);

            iv = sig_h (aA2[0] + aB2[0] + pc1.x);
            fv = sig_h (aA2[1] + aB2[1] + pc1.y);
            gv = tanh_f(aA3[0] + aB3[0] + pc1.z);
            ov = sig_h (aA3[1] + aB3[1] + pc1.w);
            c1 = fv * c1 + iv * gv;
            h1 = ov * tanh_f(c1);

            // STS early
            __half2 hhi = __floats2half2_rn(h0, h1);
            *(__half2*)&An[srow * AS2 + j0] = hhi;
        }

        // post-STS independent work (overlaps store drain)
        pc0 = pn0; pc1 = pn1;
        if (t + 2 < TT) {
            pn0 = *(const float4*)(pp + (size_t)(t + 2) * 256);
            pn1 = *(const float4*)(pp + (size_t)(t + 2) * 256 + 4);
        } else {
            pn0 = make_float4(0.f, 0.f, 0.f, 0.f); pn1 = pn0;
        }

        __syncthreads();
    }

    sred[srow * 64 + j0] = h0 * wf0;
    sred[srow * 64 + j1] = h1 * wf1;
    __syncthreads();
    if (tid < 8) {
        float acc = __ldg(bfc);
#pragma unroll
        for (int k = 0; k < 64; k++) acc += sred[tid * 64 + k];
        out[s0 + tid] = acc;
    }
}

// =====================================================================
extern "C" void kernel_launch(void* const* d_in, const int* in_sizes, int n_in,
                              void* d_out, int out_size)
{
    const float* x     = (const float*)d_in[0];
    const float* Wih_f = (const float*)d_in[1];
    const float* Whh_f = (const float*)d_in[2];
    const float* b_f   = (const float*)d_in[3];
    const float* Wih_b = (const float*)d_in[4];
    const float* Whh_b = (const float*)d_in[5];
    const float* b_b   = (const float*)d_in[6];
    const float* Wih2  = (const float*)d_in[7];
    const float* Whh2  = (const float*)d_in[8];
    const float* b2    = (const float*)d_in[9];
    const float* Wfc   = (const float*)d_in[10];
    const float* bfc   = (const float*)d_in[11];
    float* out = (float*)d_out;

    build_B<<<256, 256>>>(Wih_f, Whh_f, Wih_b, Whh_b, Wih2, Whh2);
    l1_scan<<<64, 256>>>(x, b_f, b_b);
    pre2_gemm<<<(BB * TT) / 128, 256>>>(b2);
    l2_scan<<<32, 256>>>(Wfc, bfc, out);
}

// round 14
// speedup vs baseline: 1.1920x; 1.1920x over previous
#include <cuda_runtime.h>
#include <cuda_fp16.h>
#include <cstdint>

#define BB 256
#define TT 2048

// ---------- scratch ----------
__device__ __half g_out1h[(size_t)BB * TT * 128];     // layer-1 output fp16 [B,T,128] (fwd|bwd)
__device__ float  g_pre2p[(size_t)BB * TT * 256];     // l2 input preact, permuted, bias folded (i,f,o pre-halved)
__device__ __half g_B1[2][256 * 80];                  // l1 fused B [n][k]: [Whh_hi(64)|Wih_hi(4)|Wih_hi(4)|0(8)]
__device__ __half g_B2s[256 * 64];                    // l2 scan B: Whh2_hi, i/f/o halved
__device__ __half g_B2i[256 * 128];                   // pre2 GEMM B: Wih2 fp16, col n2=j*4+gate, i/f/o halved

// ---------- helpers ----------
__device__ __forceinline__ float tanh_f(float x) {
    float y; asm("tanh.approx.f32 %0, %1;" : "=f"(y) : "f"(x)); return y;
}
// x is PRE-HALVED preactivation
__device__ __forceinline__ float sig_h(float x) {
    return fmaf(tanh_f(x), 0.5f, 0.5f);
}
__device__ __forceinline__ __half hi_h(float v) { return __float2half_rn(v); }
__device__ __forceinline__ __half lo_h(float v) {
    return __float2half_rn(v - __half2float(__float2half_rn(v)));
}
__device__ __forceinline__ uint32_t smem_u32(const void* p) {
    uint32_t a;
    asm("{ .reg .u64 t; cvta.to.shared.u64 t, %1; cvt.u32.u64 %0, t; }" : "=r"(a) : "l"(p));
    return a;
}
__device__ __forceinline__ void ldsm4(uint32_t* r, uint32_t addr) {
    asm volatile("ldmatrix.sync.aligned.m8n8.x4.shared.b16 {%0,%1,%2,%3}, [%4];"
                 : "=r"(r[0]), "=r"(r[1]), "=r"(r[2]), "=r"(r[3]) : "r"(addr));
}
__device__ __forceinline__ void mma16816(float* d, const uint32_t* a, const uint32_t* b) {
    asm volatile("mma.sync.aligned.m16n8k16.row.col.f32.f16.f16.f32 "
                 "{%0,%1,%2,%3},{%4,%5,%6,%7},{%8,%9},{%0,%1,%2,%3};"
                 : "+f"(d[0]), "+f"(d[1]), "+f"(d[2]), "+f"(d[3])
                 : "r"(a[0]), "r"(a[1]), "r"(a[2]), "r"(a[3]), "r"(b[0]), "r"(b[1]));
}

// gate-permuted column map (adjacent-j):
// tile = n>>3, c = n&7; wq = tile>>2, u = (tile>>1)&1, odd = tile&1
// j = wq*8 + 2*(c>>1) + u ; gate = 2*odd + (c&1) ; row = gate*64 + j
__device__ __forceinline__ int perm_row(int n) {
    int tile = n >> 3, c = n & 7;
    int wq = tile >> 2, u = (tile >> 1) & 1, odd = tile & 1;
    int j = wq * 8 + 2 * (c >> 1) + u;
    int gate = 2 * odd + (c & 1);
    return gate * 64 + j;
}

// =====================================================================
// Build fused B matrices (sigmoid-gate rows pre-halved).
// =====================================================================
__global__ void build_B(const float* __restrict__ Wih_f, const float* __restrict__ Whh_f,
                        const float* __restrict__ Wih_b, const float* __restrict__ Whh_b,
                        const float* __restrict__ Wih2,  const float* __restrict__ Whh2)
{
    const int n = blockIdx.x;
    const int k = threadIdx.x;
    const int r = perm_row(n);
    const float s = ((r >> 6) == 2) ? 1.f : 0.5f;   // g gate unscaled

    if (k < 80) {
        __half vf, vb;
        if      (k < 64) { vf = hi_h(s * Whh_f[r * 64 + k]);        vb = hi_h(s * Whh_b[r * 64 + k]); }
        else if (k < 68) { vf = hi_h(s * Wih_f[r * 4 + (k - 64)]);  vb = hi_h(s * Wih_b[r * 4 + (k - 64)]); }
        else if (k < 72) { vf = hi_h(s * Wih_f[r * 4 + (k - 68)]);  vb = hi_h(s * Wih_b[r * 4 + (k - 68)]); }
        else             { vf = __ushort_as_half(0);                vb = __ushort_as_half(0); }
        g_B1[0][n * 80 + k] = vf;
        g_B1[1][n * 80 + k] = vb;
    }
    if (k < 64) {
        g_B2s[n * 64 + k] = hi_h(s * Whh2[r * 64 + k]);
    }
    if (k < 128) {
        const int g2 = n & 3;
        const int r2 = g2 * 64 + (n >> 2);
        const float s2 = (g2 == 2) ? 1.f : 0.5f;
        g_B2i[n * 128 + k] = __float2half_rn(s2 * Wih2[r2 * 128 + k]);
    }
}

// =====================================================================
// Layer-1 scan: 4 samples/block, one direction. 128 blocks, 256 threads.
// A[16 x 80] fp16 (stride 88, rows 4-15 zero): [h_hi(64)|x_hi(4)|x_lo(4)].
// 5 k-tiles. Epilogue: shfl-redistributed, 1 cell per lane, fp32 tanh.
// =====================================================================
#define AS1 88
__global__ __launch_bounds__(256, 1)
void l1_scan(const float* __restrict__ x,
             const float* __restrict__ b_f, const float* __restrict__ b_b)
{
    const int grp = blockIdx.x >> 1;
    const int dir = blockIdx.x & 1;
    const int s0  = grp * 4;
    const int tid = threadIdx.x, lane = tid & 31, w = tid >> 5;

    __shared__ __half A[2 * 16 * AS1];

    for (int i = tid; i < 2 * 16 * AS1; i += 256) A[i] = __ushort_as_half(0);

    uint32_t bf[4][5][2];
    {
        const __half* B = g_B1[dir];
#pragma unroll
        for (int tt = 0; tt < 4; tt++) {
            const int n = (w * 4 + tt) * 8 + (lane >> 2);
#pragma unroll
            for (int kt = 0; kt < 5; kt++) {
                const __half* p = B + (size_t)n * 80 + kt * 16 + 2 * (lane & 3);
                bf[tt][kt][0] = *(const uint32_t*)p;
                bf[tt][kt][1] = *(const uint32_t*)(p + 8);
            }
        }
    }

    // per-lane cell identity: lanes 0-15 -> cell j0, lanes 16-31 -> cell j1
    const int srowc = (lane & 15) >> 2;                        // sample row 0..3
    const int jc    = w * 8 + 2 * (lane & 3) + (lane >> 4);    // gate index
    const float* bv = dir ? b_b : b_f;
    const float bic = 0.5f * bv[jc];
    const float bfc_ = 0.5f * bv[64 + jc];
    const float bgc = bv[128 + jc];
    const float boc = 0.5f * bv[192 + jc];

    const uint32_t lrow = lane & 15, lcol = (lane >> 4) * 8;
    const uint32_t aaddr0 = smem_u32(A) + (lrow * AS1 + lcol) * 2;
    const uint32_t aaddr1 = aaddr0 + 16 * AS1 * 2;

    const int step = dir ? -1 : 1;
    const int t0   = dir ? TT - 1 : 0;

    // x feeder: threads 0..15 (sample fsx, component comp)
    const bool xf = tid < 16;
    const int fsx = tid >> 2, comp = tid & 3;
    const float* xp = x + ((size_t)(s0 + fsx) * TT + t0) * 4 + comp;
    float vn = 0.f, vi = 0.f;
    if (xf) {
        float v0 = __ldg(xp);
        A[fsx * AS1 + 64 + comp] = hi_h(v0);
        A[fsx * AS1 + 68 + comp] = lo_h(v0);
        vn = __ldg(xp + step * 4);
        vi = __ldg(xp + 2 * step * 4);
    }
    __syncthreads();

    // output flush identity: threads 0..63 (4 samples x 16 chunks)
    const int ffs = tid >> 4, ffc = tid & 15;
    __half* fout = g_out1h + (size_t)(s0 + ffs) * TT * 128 + dir * 64 + ffc * 4;

    float c = 0.f;

    for (int t = 0; t < TT; t++) {
        const int cur = t & 1, nxt = cur ^ 1;
        const uint32_t aaddr = cur ? aaddr1 : aaddr0;
        __half* An = A + nxt * 16 * AS1;

        // 2-way split k accumulation (kt 0-2 / 3-4)
        float aA0[4], aB0[4], aA1[4], aB1[4];
        float aA2[4], aB2[4], aA3[4], aB3[4];
#pragma unroll
        for (int q = 0; q < 4; q++) {
            aA0[q] = 0.f; aB0[q] = 0.f; aA1[q] = 0.f; aB1[q] = 0.f;
            aA2[q] = 0.f; aB2[q] = 0.f; aA3[q] = 0.f; aB3[q] = 0.f;
        }
#pragma unroll
        for (int kt = 0; kt < 5; kt++) {
            uint32_t a[4];
            ldsm4(a, aaddr + kt * 32);
            if (kt < 3) {
                mma16816(aA0, a, bf[0][kt]);
                mma16816(aA1, a, bf[1][kt]);
                mma16816(aA2, a, bf[2][kt]);
                mma16816(aA3, a, bf[3][kt]);
            } else {
                mma16816(aB0, a, bf[0][kt]);
                mma16816(aB1, a, bf[1][kt]);
                mma16816(aB2, a, bf[2][kt]);
                mma16816(aB3, a, bf[3][kt]);
            }
        }

        // flush previous step's h (coalesced)
        if (t && tid < 64) {
            const __half* Ac = A + cur * 16 * AS1;
            uint2 v = *(const uint2*)(Ac + ffs * AS1 + ffc * 4);
            *(uint2*)(fout + (size_t)(t0 + (t - 1) * step) * 128) = v;
        }

        if (xf) {
            An[fsx * AS1 + 64 + comp] = hi_h(vn);
            An[fsx * AS1 + 68 + comp] = lo_h(vn);
            vn = vi;
            vi = (t + 3 < TT) ? __ldg(xp + (size_t)(t + 3) * step * 4) : 0.f;
        }

        // epilogue: combine splits, shfl cell-1 sums to lanes 16-31, 1 cell/lane
        {
            float s_i0 = aA0[0] + aB0[0], s_f0 = aA0[1] + aB0[1];
            float s_g0 = aA1[0] + aB1[0], s_o0 = aA1[1] + aB1[1];
            float s_i1 = aA2[0] + aB2[0], s_f1 = aA2[1] + aB2[1];
            float s_g1 = aA3[0] + aB3[0], s_o1 = aA3[1] + aB3[1];

            const int src = lane & 15;
            float ti = __shfl_sync(0xffffffffu, s_i1, src);
            float tf = __shfl_sync(0xffffffffu, s_f1, src);
            float tg = __shfl_sync(0xffffffffu, s_g1, src);
            float to = __shfl_sync(0xffffffffu, s_o1, src);

            float si = (lane < 16) ? s_i0 : ti;
            float sf = (lane < 16) ? s_f0 : tf;
            float sg = (lane < 16) ? s_g0 : tg;
            float so = (lane < 16) ? s_o0 : to;

            float iv = sig_h (si + bic);
            float fv = sig_h (sf + bfc_);
            float gv = tanh_f(sg + bgc);
            float ov = sig_h (so + boc);
            c = fmaf(fv, c, iv * gv);
            float h = ov * tanh_f(c);

            An[srowc * AS1 + jc] = hi_h(h);
        }
        __syncthreads();
    }

    if (tid < 64) {
        uint2 v = *(const uint2*)(A + ffs * AS1 + ffc * 4);
        *(uint2*)(fout + (size_t)(t0 + (TT - 1) * step) * 128) = v;
    }
}

// =====================================================================
// pre2 GEMM: g_pre2p[m, n2] = sum_k out1h[m,k] * B2i[n2,k] + bias (scaled)
// =====================================================================
#define ASG 136
__global__ __launch_bounds__(256, 2)
void pre2_gemm(const float* __restrict__ b2)
{
    const int m0 = blockIdx.x * 128;
    const int tid = threadIdx.x, lane = tid & 31, w = tid >> 5;

    __shared__ __half As[128 * ASG];

    {
        const uint4* src = (const uint4*)(g_out1h + (size_t)m0 * 128);
        for (int i = tid; i < 128 * 16; i += 256) {
            int rr = i >> 4, cc = i & 15;
            *(uint4*)&As[rr * ASG + cc * 8] = __ldg(src + i);
        }
    }
    __syncthreads();

    const uint32_t aaddr = smem_u32(As) + (((w * 16) + (lane & 15)) * ASG + (lane >> 4) * 8) * 2;

    float* outp = g_pre2p + (size_t)(m0 + w * 16) * 256;
    const int row0 = lane >> 2;

#pragma unroll 1
    for (int ng = 0; ng < 8; ng++) {
        uint32_t bfr[4][8][2];
#pragma unroll
        for (int tt = 0; tt < 4; tt++) {
            const int n = ng * 32 + tt * 8 + (lane >> 2);
#pragma unroll
            for (int kt = 0; kt < 8; kt++) {
                const __half* p = g_B2i + (size_t)n * 128 + kt * 16 + 2 * (lane & 3);
                bfr[tt][kt][0] = *(const uint32_t*)p;
                bfr[tt][kt][1] = *(const uint32_t*)(p + 8);
            }
        }

        float acc[4][4];
#pragma unroll
        for (int i = 0; i < 4; i++) { acc[i][0] = 0.f; acc[i][1] = 0.f; acc[i][2] = 0.f; acc[i][3] = 0.f; }
#pragma unroll
        for (int kt = 0; kt < 8; kt++) {
            uint32_t a[4];
            ldsm4(a, aaddr + kt * 32);
            mma16816(acc[0], a, bfr[0][kt]);
            mma16816(acc[1], a, bfr[1][kt]);
            mma16816(acc[2], a, bfr[2][kt]);
            mma16816(acc[3], a, bfr[3][kt]);
        }

#pragma unroll
        for (int tt = 0; tt < 4; tt++) {
            const int col = ng * 32 + tt * 8 + 2 * (lane & 3);
            const int ra = (col & 3) * 64 + (col >> 2);
            const int rb = ((col + 1) & 3) * 64 + ((col + 1) >> 2);
            const float sa = ((col & 3) == 2) ? 1.f : 0.5f;
            const float ba = __ldg(b2 + ra) * sa;
            const float bb = __ldg(b2 + rb) * 0.5f;
            float2 v0 = make_float2(acc[tt][0] + ba, acc[tt][1] + bb);
            float2 v1 = make_float2(acc[tt][2] + ba, acc[tt][3] + bb);
            *(float2*)(outp + (size_t)row0 * 256 + col)       = v0;
            *(float2*)(outp + (size_t)(row0 + 8) * 256 + col) = v1;
        }
    }
}

// =====================================================================
// Layer-2 scan: 4 samples/block, 64 blocks, 256 threads. K=64, 4 kt.
// Shfl-redistributed epilogue, 1 cell/lane. Fused FC.
// =====================================================================
#define AS2 72
__global__ __launch_bounds__(256, 1)
void l2_scan(const float* __restrict__ Wfc, const float* __restrict__ bfc,
             float* __restrict__ out)
{
    const int s0  = blockIdx.x * 4;
    const int tid = threadIdx.x, lane = tid & 31, w = tid >> 5;

    __shared__ __half A[2 * 16 * AS2];
    __shared__ float  sred[4 * 64];

    for (int i = tid; i < 2 * 16 * AS2; i += 256) A[i] = __ushort_as_half(0);

    uint32_t bf[4][4][2];
#pragma unroll
    for (int tt = 0; tt < 4; tt++) {
        const int n = (w * 4 + tt) * 8 + (lane >> 2);
#pragma unroll
        for (int kt = 0; kt < 4; kt++) {
            const __half* p = g_B2s + (size_t)n * 64 + kt * 16 + 2 * (lane & 3);
            bf[tt][kt][0] = *(const uint32_t*)p;
            bf[tt][kt][1] = *(const uint32_t*)(p + 8);
        }
    }

    // per-lane cell identity
    const int srowc = (lane & 15) >> 2;
    const int jc    = w * 8 + 2 * (lane & 3) + (lane >> 4);
    const float wfc_ = __ldg(Wfc + jc);

    const uint32_t lrow = lane & 15, lcol = (lane >> 4) * 8;
    const uint32_t aaddr0 = smem_u32(A) + (lrow * AS2 + lcol) * 2;
    const uint32_t aaddr1 = aaddr0 + 16 * AS2 * 2;

    // pre2 stream: one (i,f,g,o) quad per lane (its own cell), depth-3 prefetch
    const float* pp = g_pre2p + (size_t)(s0 + srowc) * TT * 256 + jc * 4;
    float4 pc = *(const float4*)(pp);
    float4 pn = *(const float4*)(pp + 256);
    float4 pi = *(const float4*)(pp + 512);
    __syncthreads();

    float c = 0.f, h = 0.f;

    for (int t = 0; t < TT; t++) {
        const int cur = t & 1, nxt = cur ^ 1;
        const uint32_t aaddr = cur ? aaddr1 : aaddr0;
        __half* An = A + nxt * 16 * AS2;

        float aA0[4], aB0[4], aA1[4], aB1[4];
        float aA2[4], aB2[4], aA3[4], aB3[4];
#pragma unroll
        for (int q = 0; q < 4; q++) {
            aA0[q] = 0.f; aB0[q] = 0.f; aA1[q] = 0.f; aB1[q] = 0.f;
            aA2[q] = 0.f; aB2[q] = 0.f; aA3[q] = 0.f; aB3[q] = 0.f;
        }
#pragma unroll
        for (int kt = 0; kt < 4; kt++) {
            uint32_t a[4];
            ldsm4(a, aaddr + kt * 32);
            if (kt < 2) {
                mma16816(aA0, a, bf[0][kt]);
                mma16816(aA1, a, bf[1][kt]);
                mma16816(aA2, a, bf[2][kt]);
                mma16816(aA3, a, bf[3][kt]);
            } else {
                mma16816(aB0, a, bf[0][kt]);
                mma16816(aB1, a, bf[1][kt]);
                mma16816(aB2, a, bf[2][kt]);
                mma16816(aB3, a, bf[3][kt]);
            }
        }

        float4 pf;
        if (t + 3 < TT) pf = *(const float4*)(pp + (size_t)(t + 3) * 256);
        else            pf = make_float4(0.f, 0.f, 0.f, 0.f);

        // epilogue: shfl cell-1 sums to lanes 16-31, 1 cell/lane
        {
            float s_i0 = aA0[0] + aB0[0], s_f0 = aA0[1] + aB0[1];
            float s_g0 = aA1[0] + aB1[0], s_o0 = aA1[1] + aB1[1];
            float s_i1 = aA2[0] + aB2[0], s_f1 = aA2[1] + aB2[1];
            float s_g1 = aA3[0] + aB3[0], s_o1 = aA3[1] + aB3[1];

            const int src = lane & 15;
            float ti = __shfl_sync(0xffffffffu, s_i1, src);
            float tf = __shfl_sync(0xffffffffu, s_f1, src);
            float tg = __shfl_sync(0xffffffffu, s_g1, src);
            float to = __shfl_sync(0xffffffffu, s_o1, src);

            float si = (lane < 16) ? s_i0 : ti;
            float sf = (lane < 16) ? s_f0 : tf;
            float sg = (lane < 16) ? s_g0 : tg;
            float so = (lane < 16) ? s_o0 : to;

            float iv = sig_h (si + pc.x);
            float fv = sig_h (sf + pc.y);
            float gv = tanh_f(sg + pc.z);
            float ov = sig_h (so + pc.w);
            c = fmaf(fv, c, iv * gv);
            h = ov * tanh_f(c);

            An[srowc * AS2 + jc] = hi_h(h);
        }

        pc = pn; pn = pi; pi = pf;
        __syncthreads();
    }

    // fused FC on final h
    sred[srowc * 64 + jc] = h * wfc_;
    __syncthreads();
    if (tid < 4) {
        float acc = __ldg(bfc);
#pragma unroll
        for (int k = 0; k < 64; k++) acc += sred[tid * 64 + k];
        out[s0 + tid] = acc;
    }
}

// =====================================================================
extern "C" void kernel_launch(void* const* d_in, const int* in_sizes, int n_in,
                              void* d_out, int out_size)
{
    const float* x     = (const float*)d_in[0];
    const float* Wih_f = (const float*)d_in[1];
    const float* Whh_f = (const float*)d_in[2];
    const float* b_f   = (const float*)d_in[3];
    const float* Wih_b = (const float*)d_in[4];
    const float* Whh_b = (const float*)d_in[5];
    const float* b_b   = (const float*)d_in[6];
    const float* Wih2  = (const float*)d_in[7];
    const float* Whh2  = (const float*)d_in[8];
    const float* b2    = (const float*)d_in[9];
    const float* Wfc   = (const float*)d_in[10];
    const float* bfc   = (const float*)d_in[11];
    float* out = (float*)d_out;

    build_B<<<256, 256>>>(Wih_f, Whh_f, Wih_b, Whh_b, Wih2, Whh2);
    l1_scan<<<128, 256>>>(x, b_f, b_b);
    pre2_gemm<<<(BB * TT) / 128, 256>>>(b2);
    l2_scan<<<64, 256>>>(Wfc, bfc, out);
}

// round 15
// speedup vs baseline: 1.5122x; 1.2686x over previous
#include <cuda_runtime.h>
#include <cuda_fp16.h>
#include <cstdint>

#define BB 256
#define TT 2048

// ---------- scratch ----------
__device__ __half g_out1h[(size_t)BB * TT * 128];   // layer-1 output fp16 [B,T,128] (fwd|bwd)
__device__ float  g_pre2p[(size_t)BB * TT * 256];   // l2 input preact, permuted [s][t][j*4+gate], bias folded, i/f/o pre-halved
__device__ __half g_B2i[256 * 128];                 // pre2 GEMM B: Wih2 fp16, col n2=j*4+gate, i/f/o halved

// ---------- helpers ----------
__device__ __forceinline__ float tanh_f(float x) {
    float y; asm("tanh.approx.f32 %0, %1;" : "=f"(y) : "f"(x)); return y;
}
__device__ __forceinline__ float sig_h(float x) {       // x pre-halved
    return fmaf(tanh_f(x), 0.5f, 0.5f);
}
__device__ __forceinline__ __half hi_h(float v) { return __float2half_rn(v); }
__device__ __forceinline__ __half lo_h(float v) {
    return __float2half_rn(v - __half2float(__float2half_rn(v)));
}
__device__ __forceinline__ uint32_t pack2(float a, float b) {
    __half2 h = __floats2half2_rn(a, b);
    return *(uint32_t*)&h;
}
__device__ __forceinline__ uint32_t smem_u32(const void* p) {
    uint32_t a;
    asm("{ .reg .u64 t; cvta.to.shared.u64 t, %1; cvt.u32.u64 %0, t; }" : "=r"(a) : "l"(p));
    return a;
}
__device__ __forceinline__ void ldsm4(uint32_t* r, uint32_t addr) {
    asm volatile("ldmatrix.sync.aligned.m8n8.x4.shared.b16 {%0,%1,%2,%3}, [%4];"
                 : "=r"(r[0]), "=r"(r[1]), "=r"(r[2]), "=r"(r[3]) : "r"(addr));
}
__device__ __forceinline__ void ldsm4t(uint32_t* r, uint32_t addr) {
    asm volatile("ldmatrix.sync.aligned.m8n8.x4.trans.shared.b16 {%0,%1,%2,%3}, [%4];"
                 : "=r"(r[0]), "=r"(r[1]), "=r"(r[2]), "=r"(r[3]) : "r"(addr));
}
__device__ __forceinline__ void ldsm2t(uint32_t* r, uint32_t addr) {
    asm volatile("ldmatrix.sync.aligned.m8n8.x2.trans.shared.b16 {%0,%1}, [%2];"
                 : "=r"(r[0]), "=r"(r[1]) : "r"(addr));
}
__device__ __forceinline__ void mma16816(float* d, const uint32_t* a, const uint32_t* b) {
    asm volatile("mma.sync.aligned.m16n8k16.row.col.f32.f16.f16.f32 "
                 "{%0,%1,%2,%3},{%4,%5,%6,%7},{%8,%9},{%0,%1,%2,%3};"
                 : "+f"(d[0]), "+f"(d[1]), "+f"(d[2]), "+f"(d[3])
                 : "r"(a[0]), "r"(a[1]), "r"(a[2]), "r"(a[3]), "r"(b[0]), "r"(b[1]));
}

// =====================================================================
// pre2 GEMM B build (unchanged semantics from R14): col n2 = j*4+gate
// =====================================================================
__global__ void build_B2(const float* __restrict__ Wih2)
{
    const int n = blockIdx.x, k = threadIdx.x;
    const int g2 = n & 3;
    const int r2 = g2 * 64 + (n >> 2);
    const float s2 = (g2 == 2) ? 1.f : 0.5f;
    g_B2i[n * 128 + k] = __float2half_rn(s2 * Wih2[r2 * 128 + k]);
}

// =====================================================================
// Layer-1 scan (FLIPPED): gates on M (A = weights in regs), samples on N
// (B = h via ldmatrix.trans, duplicated cols {h,h} at 2s,2s+1).
// 4 samples/block, 128 blocks, 256 threads. K: h(64)=4kt + x(8)+pad=1kt.
// Every lane owns exactly one cell (j = 8w + (lane>>2), s = lane&3).
// =====================================================================
#define HR1 80
__global__ __launch_bounds__(256, 1)
void l1_scan(const float* __restrict__ x,
             const float* __restrict__ Wih_f, const float* __restrict__ Whh_f, const float* __restrict__ b_f,
             const float* __restrict__ Wih_b, const float* __restrict__ Whh_b, const float* __restrict__ b_b)
{
    const int grp = blockIdx.x >> 1, dir = blockIdx.x & 1;
    const int s0  = grp * 4;
    const int tid = threadIdx.x, lane = tid & 31, w = tid >> 5;

    const float* Wih = dir ? Wih_b : Wih_f;
    const float* Whh = dir ? Whh_b : Whh_f;
    const float* bv  = dir ? b_b   : b_f;

    __shared__ __half Hs[2][HR1 * 8];   // [k-row][8 cols = dup-sample pairs]

    for (int i = tid; i < 2 * HR1 * 8; i += 256) ((__half*)Hs)[i] = __ushort_as_half(0);

    const int jr = lane >> 2;           // row-in-tile 0..7
    const int j  = w * 8 + jr;          // cell index
    const int sl = lane & 3;            // sample
    const int k0 = 2 * (lane & 3);      // A-fragment k offset

    // A fragments: tile0 rows0-7 = i[j] (x0.5), rows8-15 = f[j] (x0.5);
    //              tile1 rows0-7 = g[j] (x1),   rows8-15 = o[j] (x0.5)
    uint32_t af[2][5][4];
#pragma unroll
    for (int tt = 0; tt < 2; tt++) {
        const int rA = (tt == 0 ? 0 : 2) * 64 + j;
        const int rB = (tt == 0 ? 1 : 3) * 64 + j;
        const float sA = (tt == 1) ? 1.f : 0.5f;
        const float sB = 0.5f;
#pragma unroll
        for (int kt = 0; kt < 5; kt++) {
            float a00, a01, a10, a11, a20, a21, a30, a31;
            if (kt < 4) {
                const float* pA = Whh + rA * 64 + kt * 16;
                const float* pB = Whh + rB * 64 + kt * 16;
                a00 = pA[k0];     a01 = pA[k0 + 1];
                a10 = pB[k0];     a11 = pB[k0 + 1];
                a20 = pA[k0 + 8]; a21 = pA[k0 + 9];
                a30 = pB[k0 + 8]; a31 = pB[k0 + 9];
            } else {
                // k-rows 64-67 = x_hi, 68-71 = x_lo (W_hi both: W*(x_hi+x_lo)), 72-79 = 0
                a00 = (k0     < 4) ? Wih[rA * 4 + k0]         : Wih[rA * 4 + k0 - 4];
                a01 = (k0 + 1 < 4) ? Wih[rA * 4 + k0 + 1]     : Wih[rA * 4 + k0 - 3];
                a10 = (k0     < 4) ? Wih[rB * 4 + k0]         : Wih[rB * 4 + k0 - 4];
                a11 = (k0 + 1 < 4) ? Wih[rB * 4 + k0 + 1]     : Wih[rB * 4 + k0 - 3];
                a20 = 0.f; a21 = 0.f; a30 = 0.f; a31 = 0.f;
            }
            af[tt][kt][0] = pack2(sA * a00, sA * a01);
            af[tt][kt][1] = pack2(sB * a10, sB * a11);
            af[tt][kt][2] = pack2(sA * a20, sA * a21);
            af[tt][kt][3] = pack2(sB * a30, sB * a31);
        }
    }

    const float bi  = 0.5f * bv[j];
    const float bfv = 0.5f * bv[64 + j];
    const float bg  = bv[128 + j];
    const float bo  = 0.5f * bv[192 + j];

    const uint32_t base0  = smem_u32(Hs[0]);
    const uint32_t bstr   = HR1 * 8 * 2;
    const uint32_t adr1_0 = base0 + lane * 16;                 // k rows 0-31  (kt0,1)
    const uint32_t adr2_0 = base0 + (32 + lane) * 16;          // k rows 32-63 (kt2,3)
    const uint32_t adr3_0 = base0 + (64 + (lane & 15)) * 16;   // k rows 64-79 (kt4)

    const int step = dir ? -1 : 1;
    const int t0g  = dir ? TT - 1 : 0;

    // x feeder: threads 0..15: sample fsx, component comp
    const bool xf = tid < 16;
    const int fsx = tid >> 2, comp = tid & 3;
    const float* xp = x + ((size_t)(s0 + fsx) * TT + t0g) * 4 + comp;
    float vn = 0.f, vi = 0.f;
    if (xf) {
        float v0 = __ldg(xp);
        __half h0 = hi_h(v0), l0 = lo_h(v0);
        *(__half2*)&Hs[0][(64 + comp) * 8 + 2 * fsx] = __halves2half2(h0, h0);
        *(__half2*)&Hs[0][(68 + comp) * 8 + 2 * fsx] = __halves2half2(l0, l0);
        vn = __ldg(xp + step * 4);
        vi = __ldg(xp + 2 * step * 4);
    }
    __syncthreads();

    __half* outp = g_out1h + ((size_t)(s0 + sl) * TT + t0g) * 128 + dir * 64 + j;

    float c = 0.f;
    for (int t = 0; t < TT; t++) {
        const int nxt = (t & 1) ^ 1;
        const uint32_t off = (t & 1) ? bstr : 0;

        uint32_t bA[4], bB[4], bC[2];
        ldsm4t(bA, adr1_0 + off);
        ldsm4t(bB, adr2_0 + off);
        ldsm2t(bC, adr3_0 + off);

        // k-splits: A-set {kt0,kt1,kt4}, B-set {kt2,kt3}
        float t0A[4] = {0,0,0,0}, t0B[4] = {0,0,0,0};
        float t1A[4] = {0,0,0,0}, t1B[4] = {0,0,0,0};
        mma16816(t0A, af[0][0], bA);      mma16816(t1A, af[1][0], bA);
        mma16816(t0A, af[0][1], bA + 2);  mma16816(t1A, af[1][1], bA + 2);
        mma16816(t0B, af[0][2], bB);      mma16816(t1B, af[1][2], bB);
        mma16816(t0B, af[0][3], bB + 2);  mma16816(t1B, af[1][3], bB + 2);
        mma16816(t0A, af[0][4], bC);      mma16816(t1A, af[1][4], bC);

        __half* HN = Hs[nxt];
        if (xf) {
            __half hn = hi_h(vn), ln = lo_h(vn);
            *(__half2*)&HN[(64 + comp) * 8 + 2 * fsx] = __halves2half2(hn, hn);
            *(__half2*)&HN[(68 + comp) * 8 + 2 * fsx] = __halves2half2(ln, ln);
            vn = vi;
            vi = (t + 3 < TT) ? __ldg(xp + (size_t)(t + 3) * step * 4) : 0.f;
        }

        // epilogue: one complete cell per lane (i=t0.d0, f=t0.d2, g=t1.d0, o=t1.d2)
        {
            float iv = sig_h (t0A[0] + t0B[0] + bi);
            float fv = sig_h (t0A[2] + t0B[2] + bfv);
            float gv = tanh_f(t1A[0] + t1B[0] + bg);
            float ov = sig_h (t1A[2] + t1B[2] + bo);
            c = fmaf(fv, c, iv * gv);
            float h = ov * tanh_f(c);
            __half hh = hi_h(h);
            *(__half2*)&HN[j * 8 + 2 * sl] = __halves2half2(hh, hh);
            *outp = hh;
            outp += step * 128;
        }
        __syncthreads();
    }
}

// =====================================================================
// pre2 GEMM (unchanged from R14): g_pre2p[m,n2] = out1h · B2i + bias
// =====================================================================
#define ASG 136
__global__ __launch_bounds__(256, 2)
void pre2_gemm(const float* __restrict__ b2)
{
    const int m0 = blockIdx.x * 128;
    const int tid = threadIdx.x, lane = tid & 31, w = tid >> 5;

    __shared__ __half As[128 * ASG];

    {
        const uint4* src = (const uint4*)(g_out1h + (size_t)m0 * 128);
        for (int i = tid; i < 128 * 16; i += 256) {
            int rr = i >> 4, cc = i & 15;
            *(uint4*)&As[rr * ASG + cc * 8] = __ldg(src + i);
        }
    }
    __syncthreads();

    const uint32_t aaddr = smem_u32(As) + (((w * 16) + (lane & 15)) * ASG + (lane >> 4) * 8) * 2;

    float* outp = g_pre2p + (size_t)(m0 + w * 16) * 256;
    const int row0 = lane >> 2;

#pragma unroll 1
    for (int ng = 0; ng < 8; ng++) {
        uint32_t bfr[4][8][2];
#pragma unroll
        for (int tt = 0; tt < 4; tt++) {
            const int n = ng * 32 + tt * 8 + (lane >> 2);
#pragma unroll
            for (int kt = 0; kt < 8; kt++) {
                const __half* p = g_B2i + (size_t)n * 128 + kt * 16 + 2 * (lane & 3);
                bfr[tt][kt][0] = *(const uint32_t*)p;
                bfr[tt][kt][1] = *(const uint32_t*)(p + 8);
            }
        }

        float acc[4][4];
#pragma unroll
        for (int i = 0; i < 4; i++) { acc[i][0] = 0.f; acc[i][1] = 0.f; acc[i][2] = 0.f; acc[i][3] = 0.f; }
#pragma unroll
        for (int kt = 0; kt < 8; kt++) {
            uint32_t a[4];
            ldsm4(a, aaddr + kt * 32);
            mma16816(acc[0], a, bfr[0][kt]);
            mma16816(acc[1], a, bfr[1][kt]);
            mma16816(acc[2], a, bfr[2][kt]);
            mma16816(acc[3], a, bfr[3][kt]);
        }

#pragma unroll
        for (int tt = 0; tt < 4; tt++) {
            const int col = ng * 32 + tt * 8 + 2 * (lane & 3);
            const int ra = (col & 3) * 64 + (col >> 2);
            const int rb = ((col + 1) & 3) * 64 + ((col + 1) >> 2);
            const float sa = ((col & 3) == 2) ? 1.f : 0.5f;
            const float ba = __ldg(b2 + ra) * sa;
            const float bb = __ldg(b2 + rb) * 0.5f;
            float2 v0 = make_float2(acc[tt][0] + ba, acc[tt][1] + bb);
            float2 v1 = make_float2(acc[tt][2] + ba, acc[tt][3] + bb);
            *(float2*)(outp + (size_t)row0 * 256 + col)       = v0;
            *(float2*)(outp + (size_t)(row0 + 8) * 256 + col) = v1;
        }
    }
}

// =====================================================================
// Layer-2 scan (FLIPPED): 4 samples/block, 64 blocks. K=64 = 4 kt.
// =====================================================================
#define HR2 64
__global__ __launch_bounds__(256, 1)
void l2_scan(const float* __restrict__ Whh2,
             const float* __restrict__ Wfc, const float* __restrict__ bfc,
             float* __restrict__ out)
{
    const int s0  = blockIdx.x * 4;
    const int tid = threadIdx.x, lane = tid & 31, w = tid >> 5;

    __shared__ __half Hs[2][HR2 * 8];
    __shared__ float  sred[4 * 64];

    for (int i = tid; i < 2 * HR2 * 8; i += 256) ((__half*)Hs)[i] = __ushort_as_half(0);

    const int jr = lane >> 2, j = w * 8 + jr, sl = lane & 3;
    const int k0 = 2 * (lane & 3);

    uint32_t af[2][4][4];
#pragma unroll
    for (int tt = 0; tt < 2; tt++) {
        const int rA = (tt == 0 ? 0 : 2) * 64 + j;
        const int rB = (tt == 0 ? 1 : 3) * 64 + j;
        const float sA = (tt == 1) ? 1.f : 0.5f;
        const float sB = 0.5f;
#pragma unroll
        for (int kt = 0; kt < 4; kt++) {
            const float* pA = Whh2 + rA * 64 + kt * 16;
            const float* pB = Whh2 + rB * 64 + kt * 16;
            af[tt][kt][0] = pack2(sA * pA[k0],     sA * pA[k0 + 1]);
            af[tt][kt][1] = pack2(sB * pB[k0],     sB * pB[k0 + 1]);
            af[tt][kt][2] = pack2(sA * pA[k0 + 8], sA * pA[k0 + 9]);
            af[tt][kt][3] = pack2(sB * pB[k0 + 8], sB * pB[k0 + 9]);
        }
    }
    const float wfc_ = __ldg(Wfc + j);

    const uint32_t base0  = smem_u32(Hs[0]);
    const uint32_t bstr   = HR2 * 8 * 2;
    const uint32_t adr1_0 = base0 + lane * 16;
    const uint32_t adr2_0 = base0 + (32 + lane) * 16;

    // pre2 quad stream per lane: (i,f,g,o) at cell (j, s0+sl), depth-3 prefetch
    const float* pp = g_pre2p + (size_t)(s0 + sl) * TT * 256 + j * 4;
    float4 pc = *(const float4*)pp;
    float4 pn = *(const float4*)(pp + 256);
    float4 pi = *(const float4*)(pp + 512);
    __syncthreads();

    float c = 0.f, h = 0.f;
    for (int t = 0; t < TT; t++) {
        const int nxt = (t & 1) ^ 1;
        const uint32_t off = (t & 1) ? bstr : 0;

        uint32_t bA[4], bB[4];
        ldsm4t(bA, adr1_0 + off);
        ldsm4t(bB, adr2_0 + off);

        float t0A[4] = {0,0,0,0}, t0B[4] = {0,0,0,0};
        float t1A[4] = {0,0,0,0}, t1B[4] = {0,0,0,0};
        mma16816(t0A, af[0][0], bA);      mma16816(t1A, af[1][0], bA);
        mma16816(t0A, af[0][1], bA + 2);  mma16816(t1A, af[1][1], bA + 2);
        mma16816(t0B, af[0][2], bB);      mma16816(t1B, af[1][2], bB);
        mma16816(t0B, af[0][3], bB + 2);  mma16816(t1B, af[1][3], bB + 2);

        float4 pf = (t + 3 < TT) ? *(const float4*)(pp + (size_t)(t + 3) * 256)
                                 : make_float4(0.f, 0.f, 0.f, 0.f);

        {
            float iv = sig_h (t0A[0] + t0B[0] + pc.x);
            float fv = sig_h (t0A[2] + t0B[2] + pc.y);
            float gv = tanh_f(t1A[0] + t1B[0] + pc.z);
            float ov = sig_h (t1A[2] + t1B[2] + pc.w);
            c = fmaf(fv, c, iv * gv);
            h = ov * tanh_f(c);
            __half hh = hi_h(h);
            *(__half2*)&Hs[nxt][j * 8 + 2 * sl] = __halves2half2(hh, hh);
        }
        pc = pn; pn = pi; pi = pf;
        __syncthreads();
    }

    sred[sl * 64 + j] = h * wfc_;
    __syncthreads();
    if (tid < 4) {
        float acc = __ldg(bfc);
#pragma unroll
        for (int k = 0; k < 64; k++) acc += sred[tid * 64 + k];
        out[s0 + tid] = acc;
    }
}

// =====================================================================
extern "C" void kernel_launch(void* const* d_in, const int* in_sizes, int n_in,
                              void* d_out, int out_size)
{
    const float* x     = (const float*)d_in[0];
    const float* Wih_f = (const float*)d_in[1];
    const float* Whh_f = (const float*)d_in[2];
    const float* b_f   = (const float*)d_in[3];
    const float* Wih_b = (const float*)d_in[4];
    const float* Whh_b = (const float*)d_in[5];
    const float* b_b   = (const float*)d_in[6];
    const float* Wih2  = (const float*)d_in[7];
    const float* Whh2  = (const float*)d_in[8];
    const float* b2    = (const float*)d_in[9];
    const float* Wfc   = (const float*)d_in[10];
    const float* bfc   = (const float*)d_in[11];
    float* out = (float*)d_out;

    build_B2<<<256, 128>>>(Wih2);
    l1_scan<<<128, 256>>>(x, Wih_f, Whh_f, b_f, Wih_b, Whh_b, b_b);
    pre2_gemm<<<(BB * TT) / 128, 256>>>(b2);
    l2_scan<<<64, 256>>>(Whh2, Wfc, bfc, out);
}